// round 7
// baseline (speedup 1.0000x reference)
#include <cuda_runtime.h>
#include <cuda_bf16.h>

#define HID    64
#define BATCH  16384
#define NSTEPS 100
#define DT     0.01f
#define AP_STRIDE 132   // padded k2-row stride (words) for aHi/aLo

__device__ float g_pA[128];
__device__ float g_pB[128];

__device__ __forceinline__ float exact_tanh(float v) {
    float av = fabsf(v);
    float e  = __expf(-2.0f * av);
    float r  = __fdividef(1.0f - e, 1.0f + e);
    return copysignf(r, v);
}
__device__ __forceinline__ float tanh_ap(float x) {
    float y; asm("tanh.approx.f32 %0, %1;" : "=f"(y) : "f"(x)); return y;
}
__device__ __forceinline__ unsigned pack_bf2(float lo, float hi) {
    __nv_bfloat162 v = __floats2bfloat162_rn(lo, hi);
    return *reinterpret_cast<unsigned*>(&v);
}
__device__ __forceinline__ void mma_bf16(float* c,
                                         unsigned a0, unsigned a1, unsigned a2, unsigned a3,
                                         unsigned b0, unsigned b1) {
    asm volatile("mma.sync.aligned.m16n8k16.row.col.f32.bf16.bf16.f32 "
                 "{%0,%1,%2,%3},{%4,%5,%6,%7},{%8,%9},{%0,%1,%2,%3};"
                 : "+f"(c[0]), "+f"(c[1]), "+f"(c[2]), "+f"(c[3])
                 : "r"(a0), "r"(a1), "r"(a2), "r"(a3), "r"(b0), "r"(b1));
}

__global__ void __launch_bounds__(512) sim_kernel(
    const float* __restrict__ dw,
    const float* __restrict__ X0, const float* __restrict__ R0,
    const float* __restrict__ pW1, const float* __restrict__ pb1,
    const float* __restrict__ pW2, const float* __restrict__ pb2,
    const float* __restrict__ pW3, const float* __restrict__ pb3,
    const float* __restrict__ qW1, const float* __restrict__ qb1,
    const float* __restrict__ qW2, const float* __restrict__ qb2,
    const float* __restrict__ qW3, const float* __restrict__ qb3,
    float* __restrict__ out)
{
    __shared__ __align__(16) float4   sW1q[HID];            // {w_t, w_x, w_r, b1}
    __shared__ __align__(16) unsigned aHi[32 * AP_STRIDE];  // bf16x2 h-hi [k2][sample]
    __shared__ __align__(16) unsigned aLo[32 * AP_STRIDE];  // bf16x2 h-lo
    __shared__ __align__(16) float    part[128 * 4];        // [sample][ng]
    __shared__ float2 sxr[128];
    __shared__ float  ph1[HID], pd1[HID], ptA[HID], ptB[HID];
    __shared__ float  s_p0, s_dp0, s_pi0, s_b3;
    __shared__ float  redA[16], redB[16];

    const int tid  = threadIdx.x;
    const int lane = tid & 31;
    const int w    = tid >> 5;         // 0..15
    const int g    = lane >> 2;
    const int tg   = lane & 3;
    const int mg   = w >> 2;           // m-group: rows 32mg..32mg+31
    const int ng   = w & 3;            // n-group: cols 16ng..16ng+15

    const float x0v = X0[0], r0v = R0[0];

    for (int k = tid; k < HID; k += 512)
        sW1q[k] = make_float4(qW1[k], qW1[HID + k], qW1[2 * HID + k], qb1[k]);
    if (tid == 0) s_b3 = qb3[0];

    // ---- B fragments (W2 split hi/lo), persistent in registers ----
    // [nt][kt]: n = 16ng+8nt+g, k0 = 16kt+2tg
    unsigned bH0[2][4], bH1[2][4], bL0[2][4], bL1[2][4];
    float b2a[2], b2b[2], w3a[2], w3b[2];
    #pragma unroll
    for (int nt = 0; nt < 2; ++nt) {
        int n = 16 * ng + 8 * nt + g;
        #pragma unroll
        for (int kt = 0; kt < 4; ++kt) {
            int k0 = 16 * kt + 2 * tg;
            float w00 = qW2[(k0 + 0) * HID + n];
            float w01 = qW2[(k0 + 1) * HID + n];
            float w10 = qW2[(k0 + 8) * HID + n];
            float w11 = qW2[(k0 + 9) * HID + n];
            float h00 = __bfloat162float(__float2bfloat16(w00));
            float h01 = __bfloat162float(__float2bfloat16(w01));
            float h10 = __bfloat162float(__float2bfloat16(w10));
            float h11 = __bfloat162float(__float2bfloat16(w11));
            bH0[nt][kt] = pack_bf2(h00, h01);
            bH1[nt][kt] = pack_bf2(h10, h11);
            bL0[nt][kt] = pack_bf2(w00 - h00, w01 - h01);
            bL1[nt][kt] = pack_bf2(w10 - h10, w11 - h11);
        }
        int jc = 16 * ng + 8 * nt + 2 * tg;
        b2a[nt] = qb2[jc];     b2b[nt] = qb2[jc + 1];
        w3a[nt] = qW3[jc];     w3b[nt] = qW3[jc + 1];
    }

    // ---- scalar prep (p0, dp0, pi0), exact tanh ----
    if (tid < HID) {
        int j = tid;
        float a = pW1[HID + j] * x0v + pW1[2 * HID + j] * r0v + pb1[j];
        float h = exact_tanh(a);
        ph1[j] = h;
        pd1[j] = (1.0f - h * h) * pW1[HID + j];
        float aq = qW1[HID + j] * x0v + qW1[2 * HID + j] * r0v + qb1[j];
        ptA[j] = exact_tanh(aq);
    }
    __syncthreads();
    float pa = 0.0f, qa = 0.0f, db = 0.0f;
    if (tid < HID) {
        int j = tid;
        float acc = pb2[j], dacc = 0.0f, accq = qb2[j];
        #pragma unroll 16
        for (int k = 0; k < HID; ++k) {
            float wv = pW2[k * HID + j];
            acc  += ph1[k] * wv;
            dacc += pd1[k] * wv;
            accq += ptA[k] * qW2[k * HID + j];
        }
        float h2 = exact_tanh(acc);
        float d2 = (1.0f - h2 * h2) * dacc;
        pa = h2 * pW3[j];
        db = d2 * pW3[j];
        qa = exact_tanh(accq) * qW3[j];
    }
    __syncthreads();
    if (tid < HID) { ph1[tid] = pa; pd1[tid] = qa; ptB[tid] = db; }
    __syncthreads();
    if (tid == 0) {
        float s = pb3[0], sd = 0.0f, sq = qb3[0];
        for (int k = 0; k < HID; ++k) { s += ph1[k]; sd += ptB[k]; sq += pd1[k]; }
        s_p0 = s; s_dp0 = sd; s_pi0 = sq;
    }
    __syncthreads();

    const float p0  = s_p0;
    const float dp0 = s_dp0;
    const float pi0 = s_pi0;
    const float b3v = s_b3;

    const float C_ADT  = 0.05f * 0.01f;
    const float C_STDT = 0.2f * 0.3f * 0.01f;
    const float SIG    = 0.2f;
    const float BEFF   = 0.1f;
    const float C_R1   = 0.02f - 0.5f * 0.1f * 0.1f;
    const float C_P1   = -(0.05f + 0.5f * 0.3f * 0.3f);
    const float TH     = 0.3f;

    const int b = blockIdx.x * 128 + tid;     // valid for tid<128
    float x = x0v, mn = x0v, Wsum = 0.0f, pi = pi0, Rv = r0v, p = p0, dwv = 0.0f;
    if (tid < 128) {
        dwv = dw[b * NSTEPS];
        unsigned base = (unsigned)b * 5u;
        out[base + 0] = x0v; out[base + 1] = r0v; out[base + 2] = pi0;
        out[base + 3] = -p0; out[base + 4] = -dp0;
    }

    const int sA = tid >> 2;       // phase-A sample 0..127
    const int qk = tid & 3;        // phase-A k-quarter (rows 8qk..8qk+7)

    #pragma unroll 1
    for (int i = 1; i < NSTEPS; ++i) {
        float t = (float)i * DT;
        // ---- O: gather pi (prev GEMM), store prev row, advance state ----
        if (tid < 128) {
            if (i > 1) {
                float4 pr = *reinterpret_cast<const float4*>(part + tid * 4);
                pi = b3v + ((pr.x + pr.y) + (pr.z + pr.w));
                unsigned base = ((unsigned)(i - 1) * BATCH + (unsigned)b) * 5u;
                out[base + 0] = x;  out[base + 1] = Rv; out[base + 2] = pi;
                out[base + 3] = -p; out[base + 4] = -dp0;
            }
            float dwi = dwv;
            x = x + x * C_ADT + pi * C_STDT + pi * SIG * dwi;
            mn = fminf(mn, x);
            Wsum += dwi;
            Rv = r0v * __expf(C_R1 * t + BEFF * Wsum);
            p  = p0  * __expf(C_P1 * t - TH * Wsum);
            sxr[tid] = make_float2(x, Rv);
            dwv = dw[b * NSTEPS + i];
        }
        __syncthreads();

        // ---- A: hidden layer -> bf16 hi/lo in shared (16 units/thread) ----
        {
            float2 xr = sxr[sA];
            float s0 = 2.0f * t;
            #pragma unroll
            for (int j = 0; j < 8; ++j) {
                int k = 16 * qk + 2 * j;
                float4 wa = sW1q[k];
                float4 wb = sW1q[k + 1];
                float a0 = fmaf(wa.x, s0, wa.w); a0 = fmaf(wa.y, xr.x, a0); a0 = fmaf(wa.z, xr.y, a0);
                float a1 = fmaf(wb.x, s0, wb.w); a1 = fmaf(wb.y, xr.x, a1); a1 = fmaf(wb.z, xr.y, a1);
                float h0 = tanh_ap(a0), h1v = tanh_ap(a1);
                float h0h = __bfloat162float(__float2bfloat16(h0));
                float h1h = __bfloat162float(__float2bfloat16(h1v));
                int idx = (8 * qk + j) * AP_STRIDE + sA;
                aHi[idx] = pack_bf2(h0h, h1h);
                aLo[idx] = pack_bf2(h0 - h0h, h1v - h1h);
            }
        }
        __syncthreads();

        // ---- GEMM: warp tile 32 rows x 16 cols ----
        {
            float c[2][2][4];
            #pragma unroll
            for (int m2 = 0; m2 < 2; ++m2)
                #pragma unroll
                for (int nt = 0; nt < 2; ++nt)
                    #pragma unroll
                    for (int q = 0; q < 4; ++q) c[m2][nt][q] = 0.0f;

            #pragma unroll
            for (int kt = 0; kt < 4; ++kt) {
                #pragma unroll
                for (int m2 = 0; m2 < 2; ++m2) {
                    int base = 32 * mg + 16 * m2;
                    int r0i = (8 * kt + tg) * AP_STRIDE + base + g;
                    int r1i = (8 * kt + tg + 4) * AP_STRIDE + base + g;
                    unsigned a0h = aHi[r0i], a1h = aHi[r0i + 8];
                    unsigned a2h = aHi[r1i], a3h = aHi[r1i + 8];
                    unsigned a0l = aLo[r0i], a1l = aLo[r0i + 8];
                    unsigned a2l = aLo[r1i], a3l = aLo[r1i + 8];
                    #pragma unroll
                    for (int nt = 0; nt < 2; ++nt) {
                        mma_bf16(c[m2][nt], a0h, a1h, a2h, a3h, bH0[nt][kt], bH1[nt][kt]);
                        mma_bf16(c[m2][nt], a0h, a1h, a2h, a3h, bL0[nt][kt], bL1[nt][kt]);
                        mma_bf16(c[m2][nt], a0l, a1l, a2l, a3l, bH0[nt][kt], bH1[nt][kt]);
                    }
                }
            }
            // epilogue: tanh, W3 dot, reduce over tg
            #pragma unroll
            for (int m2 = 0; m2 < 2; ++m2) {
                float vl = 0.0f, vh = 0.0f;
                #pragma unroll
                for (int nt = 0; nt < 2; ++nt) {
                    vl += fmaf(tanh_ap(c[m2][nt][0] + b2a[nt]), w3a[nt],
                               tanh_ap(c[m2][nt][1] + b2b[nt]) * w3b[nt]);
                    vh += fmaf(tanh_ap(c[m2][nt][2] + b2a[nt]), w3a[nt],
                               tanh_ap(c[m2][nt][3] + b2b[nt]) * w3b[nt]);
                }
                vl += __shfl_xor_sync(0xffffffffu, vl, 1);
                vh += __shfl_xor_sync(0xffffffffu, vh, 1);
                vl += __shfl_xor_sync(0xffffffffu, vl, 2);
                vh += __shfl_xor_sync(0xffffffffu, vh, 2);
                if (tg == 0) {
                    int base = 32 * mg + 16 * m2;
                    part[(base + g) * 4 + ng]     = vl;
                    part[(base + g + 8) * 4 + ng] = vh;
                }
            }
        }
        __syncthreads();
    }

    // ---- tail: gather pi at t_99, store row 99; final step to t_100 ----
    if (tid < 128) {
        {
            float4 pr = *reinterpret_cast<const float4*>(part + tid * 4);
            pi = b3v + ((pr.x + pr.y) + (pr.z + pr.w));
            unsigned base = ((unsigned)(NSTEPS - 1) * BATCH + (unsigned)b) * 5u;
            out[base + 0] = x;  out[base + 1] = Rv; out[base + 2] = pi;
            out[base + 3] = -p; out[base + 4] = -dp0;
        }
        float t = (float)NSTEPS * DT;
        float dwi = dwv;
        x = x + x * C_ADT + pi * C_STDT + pi * SIG * dwi;
        mn = fminf(mn, x);
        Wsum += dwi;
        Rv = r0v * __expf(C_R1 * t + BEFF * Wsum);
        p  = p0  * __expf(C_P1 * t - TH * Wsum);
        unsigned base = ((unsigned)NSTEPS * BATCH + (unsigned)b) * 5u;
        out[base + 0] = x;  out[base + 1] = Rv; out[base + 2] = pi;
        out[base + 3] = -p; out[base + 4] = -dp0;
    }

    // ---- losses ----
    float aa = 0.0f, bb = 0.0f;
    if (tid < 128) {
        float xc  = fmaxf(x, 1e-6f);
        float ux  = Rv * rsqrtf(xc);
        float uv  = 2.0f * Rv * sqrtf(xc);
        float dpn = fmaxf(1e-6f - mn, 0.0f);
        float pen = 100.0f * dpn * dpn;
        aa = p + ux; aa = aa * aa + pen;
        bb = -uv + pen;
        #pragma unroll
        for (int s = 16; s > 0; s >>= 1) {
            aa += __shfl_xor_sync(0xffffffffu, aa, s);
            bb += __shfl_xor_sync(0xffffffffu, bb, s);
        }
        if (lane == 0) { redA[w] = aa; redB[w] = bb; }
    }
    __syncthreads();
    if (tid == 0) {
        float sA2 = ((redA[0] + redA[1]) + (redA[2] + redA[3]));
        float sB2 = ((redB[0] + redB[1]) + (redB[2] + redB[3]));
        g_pA[blockIdx.x] = sA2; g_pB[blockIdx.x] = sB2;
    }
}

__global__ void finalize_kernel(float* __restrict__ out)
{
    __shared__ float rA[128], rB[128];
    int tid = threadIdx.x;
    rA[tid] = g_pA[tid]; rB[tid] = g_pB[tid];
    __syncthreads();
    for (int s = 64; s > 0; s >>= 1) {
        if (tid < s) { rA[tid] += rA[tid + s]; rB[tid] += rB[tid + s]; }
        __syncthreads();
    }
    if (tid == 0) {
        float lp  = rA[0] / (float)BATCH;
        float lpi = lp + rB[0] / (float)BATCH;
        unsigned base = (unsigned)(NSTEPS + 1) * BATCH * 5u;
        out[base + 0] = lp;
        out[base + 1] = lpi;
    }
}

extern "C" void kernel_launch(void* const* d_in, const int* in_sizes, int n_in,
                              void* d_out, int out_size)
{
    const float* dw  = (const float*)d_in[0];
    const float* X0  = (const float*)d_in[1];
    const float* R0  = (const float*)d_in[2];
    const float* pW1 = (const float*)d_in[3];  const float* pb1 = (const float*)d_in[4];
    const float* pW2 = (const float*)d_in[5];  const float* pb2 = (const float*)d_in[6];
    const float* pW3 = (const float*)d_in[7];  const float* pb3 = (const float*)d_in[8];
    const float* qW1 = (const float*)d_in[9];  const float* qb1 = (const float*)d_in[10];
    const float* qW2 = (const float*)d_in[11]; const float* qb2 = (const float*)d_in[12];
    const float* qW3 = (const float*)d_in[13]; const float* qb3 = (const float*)d_in[14];
    float* out = (float*)d_out;

    sim_kernel<<<128, 512>>>(dw, X0, R0, pW1, pb1, pW2, pb2, pW3, pb3,
                             qW1, qb1, qW2, qb2, qW3, qb3, out);
    finalize_kernel<<<1, 128>>>(out);
}

// round 9
// speedup vs baseline: 1.6819x; 1.6819x over previous
#include <cuda_runtime.h>
#include <cuda_bf16.h>

#define HID    64
#define BATCH  16384
#define NSTEPS 100
#define DT     0.01f
#define AP_STRIDE 132   // padded k2-row stride (words) for aHi/aLo

__device__ float g_pA[128];
__device__ float g_pB[128];

__device__ __forceinline__ float exact_tanh(float v) {
    float av = fabsf(v);
    float e  = __expf(-2.0f * av);
    float r  = __fdividef(1.0f - e, 1.0f + e);
    return copysignf(r, v);
}
__device__ __forceinline__ float tanh_ap(float x) {
    float y; asm("tanh.approx.f32 %0, %1;" : "=f"(y) : "f"(x)); return y;
}
__device__ __forceinline__ unsigned pack_bf2(float lo, float hi) {
    __nv_bfloat162 v = __floats2bfloat162_rn(lo, hi);
    return *reinterpret_cast<unsigned*>(&v);
}
__device__ __forceinline__ void mma_bf16(float* c,
                                         unsigned a0, unsigned a1, unsigned a2, unsigned a3,
                                         unsigned b0, unsigned b1) {
    asm volatile("mma.sync.aligned.m16n8k16.row.col.f32.bf16.bf16.f32 "
                 "{%0,%1,%2,%3},{%4,%5,%6,%7},{%8,%9},{%0,%1,%2,%3};"
                 : "+f"(c[0]), "+f"(c[1]), "+f"(c[2]), "+f"(c[3])
                 : "r"(a0), "r"(a1), "r"(a2), "r"(a3), "r"(b0), "r"(b1));
}

__global__ void __launch_bounds__(256) sim_kernel(
    const float* __restrict__ dw,
    const float* __restrict__ X0, const float* __restrict__ R0,
    const float* __restrict__ pW1, const float* __restrict__ pb1,
    const float* __restrict__ pW2, const float* __restrict__ pb2,
    const float* __restrict__ pW3, const float* __restrict__ pb3,
    const float* __restrict__ qW1, const float* __restrict__ qb1,
    const float* __restrict__ qW2, const float* __restrict__ qb2,
    const float* __restrict__ qW3, const float* __restrict__ qb3,
    float* __restrict__ out)
{
    __shared__ __align__(16) float4   sW1q[HID];            // {w_t, w_x, w_r, b1}
    __shared__ __align__(16) unsigned aHi[32 * AP_STRIDE];  // bf16x2 h-hi [k2][sample]
    __shared__ __align__(16) unsigned aLo[32 * AP_STRIDE];  // bf16x2 h-lo
    __shared__ __align__(16) float    part[128 * 4];        // [sample][ng] (2 used)
    __shared__ float  ph1[HID], pd1[HID], ptA[HID], ptB[HID];
    __shared__ float  s_p0, s_dp0, s_pi0, s_b3;
    __shared__ float  redA[8], redB[8];

    const int tid  = threadIdx.x;
    const int lane = tid & 31;
    const int w    = tid >> 5;
    const int g    = lane >> 2;
    const int tg   = lane & 3;
    const int mg   = w >> 1;           // m-group: rows 32mg..32mg+31
    const int ng   = w & 1;            // n-group: cols 32ng..32ng+31

    const float x0v = X0[0], r0v = R0[0];

    for (int k = tid; k < HID; k += 256)
        sW1q[k] = make_float4(qW1[k], qW1[HID + k], qW1[2 * HID + k], qb1[k]);
    if (tid == 0) s_b3 = qb3[0];

    // ---- B fragments (W2 split hi/lo), persistent in registers ----
    unsigned bH0[4][4], bH1[4][4], bL0[4][4], bL1[4][4];
    float b2a[4], b2b[4], w3a[4], w3b[4];
    #pragma unroll
    for (int nt = 0; nt < 4; ++nt) {
        int n = 32 * ng + 8 * nt + g;
        #pragma unroll
        for (int kt = 0; kt < 4; ++kt) {
            int k0 = 16 * kt + 2 * tg;
            float w00 = qW2[(k0 + 0) * HID + n];
            float w01 = qW2[(k0 + 1) * HID + n];
            float w10 = qW2[(k0 + 8) * HID + n];
            float w11 = qW2[(k0 + 9) * HID + n];
            float h00 = __bfloat162float(__float2bfloat16(w00));
            float h01 = __bfloat162float(__float2bfloat16(w01));
            float h10 = __bfloat162float(__float2bfloat16(w10));
            float h11 = __bfloat162float(__float2bfloat16(w11));
            bH0[nt][kt] = pack_bf2(h00, h01);
            bH1[nt][kt] = pack_bf2(h10, h11);
            bL0[nt][kt] = pack_bf2(w00 - h00, w01 - h01);
            bL1[nt][kt] = pack_bf2(w10 - h10, w11 - h11);
        }
        int jc = 32 * ng + 8 * nt + 2 * tg;
        b2a[nt] = qb2[jc];     b2b[nt] = qb2[jc + 1];
        w3a[nt] = qW3[jc];     w3b[nt] = qW3[jc + 1];
    }

    // ---- scalar prep (p0, dp0, pi0), exact tanh ----
    if (tid < HID) {
        int j = tid;
        float a = pW1[HID + j] * x0v + pW1[2 * HID + j] * r0v + pb1[j];
        float h = exact_tanh(a);
        ph1[j] = h;
        pd1[j] = (1.0f - h * h) * pW1[HID + j];
        float aq = qW1[HID + j] * x0v + qW1[2 * HID + j] * r0v + qb1[j];
        ptA[j] = exact_tanh(aq);
    }
    __syncthreads();
    float pa = 0.0f, qa = 0.0f, db = 0.0f;
    if (tid < HID) {
        int j = tid;
        float acc = pb2[j], dacc = 0.0f, accq = qb2[j];
        #pragma unroll 16
        for (int k = 0; k < HID; ++k) {
            float wv = pW2[k * HID + j];
            acc  += ph1[k] * wv;
            dacc += pd1[k] * wv;
            accq += ptA[k] * qW2[k * HID + j];
        }
        float h2 = exact_tanh(acc);
        float d2 = (1.0f - h2 * h2) * dacc;
        pa = h2 * pW3[j];
        db = d2 * pW3[j];
        qa = exact_tanh(accq) * qW3[j];
    }
    __syncthreads();
    if (tid < HID) { ph1[tid] = pa; pd1[tid] = qa; ptB[tid] = db; }
    __syncthreads();
    if (tid == 0) {
        float s = pb3[0], sd = 0.0f, sq = qb3[0];
        for (int k = 0; k < HID; ++k) { s += ph1[k]; sd += ptB[k]; sq += pd1[k]; }
        s_p0 = s; s_dp0 = sd; s_pi0 = sq;
    }
    __syncthreads();

    const float p0  = s_p0;
    const float dp0 = s_dp0;
    const float pi0 = s_pi0;
    const float b3v = s_b3;

    const float C_ADT  = 0.05f * 0.01f;
    const float C_STDT = 0.2f * 0.3f * 0.01f;
    const float SIG    = 0.2f;
    const float BEFF   = 0.1f;
    const float C_R1   = 0.02f - 0.5f * 0.1f * 0.1f;
    const float C_P1   = -(0.05f + 0.5f * 0.3f * 0.3f);
    const float TH     = 0.3f;

    // both halfk threads duplicate the full state of sample sA (bitwise identical)
    const int sA    = tid >> 1;
    const int halfk = tid & 1;
    const int b = blockIdx.x * 128 + sA;

    float x = x0v, mn = x0v, Wsum = 0.0f, pi = pi0, Rv = r0v, p = p0;
    float dwv = dw[b * NSTEPS];      // prefetch step-1 increment (both threads, same addr)
    if (halfk == 0) {
        unsigned base = (unsigned)b * 5u;
        out[base + 0] = x0v; out[base + 1] = r0v; out[base + 2] = pi0;
        out[base + 3] = -p0; out[base + 4] = -dp0;
    }

    #pragma unroll 1
    for (int i = 1; i < NSTEPS; ++i) {
        float t = (float)i * DT;
        // ---- fused: gather pi (prev GEMM), store prev row, advance state ----
        if (i > 1) {
            float2 pr = *reinterpret_cast<const float2*>(part + sA * 4);
            pi = b3v + pr.x + pr.y;
            if (halfk == 0) {
                unsigned base = ((unsigned)(i - 1) * BATCH + (unsigned)b) * 5u;
                out[base + 0] = x;  out[base + 1] = Rv; out[base + 2] = pi;
                out[base + 3] = -p; out[base + 4] = -dp0;
            }
        }
        {
            float dwi = dwv;
            x = x + x * C_ADT + pi * C_STDT + pi * SIG * dwi;
            mn = fminf(mn, x);
            Wsum += dwi;
            Rv = r0v * __expf(C_R1 * t + BEFF * Wsum);
            p  = p0  * __expf(C_P1 * t - TH * Wsum);
            dwv = dw[b * NSTEPS + i];
        }

        // ---- A: hidden layer -> bf16 hi/lo in shared (32 units/thread) ----
        {
            float s0 = 2.0f * t;
            #pragma unroll
            for (int k2 = 0; k2 < 16; ++k2) {
                int k = 32 * halfk + 2 * k2;
                float4 wa = sW1q[k];
                float4 wb = sW1q[k + 1];
                float a0 = fmaf(wa.x, s0, wa.w); a0 = fmaf(wa.y, x, a0); a0 = fmaf(wa.z, Rv, a0);
                float a1 = fmaf(wb.x, s0, wb.w); a1 = fmaf(wb.y, x, a1); a1 = fmaf(wb.z, Rv, a1);
                float h0 = tanh_ap(a0), h1v = tanh_ap(a1);
                float h0h = __bfloat162float(__float2bfloat16(h0));
                float h1h = __bfloat162float(__float2bfloat16(h1v));
                int idx = (16 * halfk + k2) * AP_STRIDE + sA;
                aHi[idx] = pack_bf2(h0h, h1h);
                aLo[idx] = pack_bf2(h0 - h0h, h1v - h1h);
            }
        }
        __syncthreads();

        // ---- GEMM: warp tile 32 rows x 32 cols ----
        {
            float c[2][4][4];
            #pragma unroll
            for (int m2 = 0; m2 < 2; ++m2)
                #pragma unroll
                for (int nt = 0; nt < 4; ++nt)
                    #pragma unroll
                    for (int q = 0; q < 4; ++q) c[m2][nt][q] = 0.0f;

            #pragma unroll
            for (int kt = 0; kt < 4; ++kt) {
                #pragma unroll
                for (int m2 = 0; m2 < 2; ++m2) {
                    int base = 32 * mg + 16 * m2;
                    int r0i = (8 * kt + tg) * AP_STRIDE + base + g;
                    int r1i = (8 * kt + tg + 4) * AP_STRIDE + base + g;
                    unsigned a0h = aHi[r0i], a1h = aHi[r0i + 8];
                    unsigned a2h = aHi[r1i], a3h = aHi[r1i + 8];
                    unsigned a0l = aLo[r0i], a1l = aLo[r0i + 8];
                    unsigned a2l = aLo[r1i], a3l = aLo[r1i + 8];
                    #pragma unroll
                    for (int nt = 0; nt < 4; ++nt) {
                        mma_bf16(c[m2][nt], a0h, a1h, a2h, a3h, bH0[nt][kt], bH1[nt][kt]);
                        mma_bf16(c[m2][nt], a0h, a1h, a2h, a3h, bL0[nt][kt], bL1[nt][kt]);
                        mma_bf16(c[m2][nt], a0l, a1l, a2l, a3l, bH0[nt][kt], bH1[nt][kt]);
                    }
                }
            }
            // epilogue: tanh, W3 dot, reduce over tg
            #pragma unroll
            for (int m2 = 0; m2 < 2; ++m2) {
                float vl = 0.0f, vh = 0.0f;
                #pragma unroll
                for (int nt = 0; nt < 4; ++nt) {
                    vl += fmaf(tanh_ap(c[m2][nt][0] + b2a[nt]), w3a[nt],
                               tanh_ap(c[m2][nt][1] + b2b[nt]) * w3b[nt]);
                    vh += fmaf(tanh_ap(c[m2][nt][2] + b2a[nt]), w3a[nt],
                               tanh_ap(c[m2][nt][3] + b2b[nt]) * w3b[nt]);
                }
                vl += __shfl_xor_sync(0xffffffffu, vl, 1);
                vh += __shfl_xor_sync(0xffffffffu, vh, 1);
                vl += __shfl_xor_sync(0xffffffffu, vl, 2);
                vh += __shfl_xor_sync(0xffffffffu, vh, 2);
                if (tg == 0) {
                    int base = 32 * mg + 16 * m2;
                    part[(base + g) * 4 + ng]     = vl;
                    part[(base + g + 8) * 4 + ng] = vh;
                }
            }
        }
        __syncthreads();
    }

    // ---- tail: gather pi at t_99, store row 99; final step to t_100 ----
    {
        float2 pr = *reinterpret_cast<const float2*>(part + sA * 4);
        pi = b3v + pr.x + pr.y;
        if (halfk == 0) {
            unsigned base = ((unsigned)(NSTEPS - 1) * BATCH + (unsigned)b) * 5u;
            out[base + 0] = x;  out[base + 1] = Rv; out[base + 2] = pi;
            out[base + 3] = -p; out[base + 4] = -dp0;
        }
        float t = (float)NSTEPS * DT;
        float dwi = dwv;
        x = x + x * C_ADT + pi * C_STDT + pi * SIG * dwi;
        mn = fminf(mn, x);
        Wsum += dwi;
        Rv = r0v * __expf(C_R1 * t + BEFF * Wsum);
        p  = p0  * __expf(C_P1 * t - TH * Wsum);
        if (halfk == 0) {
            unsigned base = ((unsigned)NSTEPS * BATCH + (unsigned)b) * 5u;
            out[base + 0] = x;  out[base + 1] = Rv; out[base + 2] = pi;
            out[base + 3] = -p; out[base + 4] = -dp0;
        }
    }

    // ---- losses (halfk==0 contributes; halves are duplicates) ----
    float aa = 0.0f, bb = 0.0f;
    if (halfk == 0) {
        float xc  = fmaxf(x, 1e-6f);
        float ux  = Rv * rsqrtf(xc);
        float uv  = 2.0f * Rv * sqrtf(xc);
        float dpn = fmaxf(1e-6f - mn, 0.0f);
        float pen = 100.0f * dpn * dpn;
        aa = p + ux; aa = aa * aa + pen;
        bb = -uv + pen;
    }
    #pragma unroll
    for (int s = 16; s > 0; s >>= 1) {
        aa += __shfl_xor_sync(0xffffffffu, aa, s);
        bb += __shfl_xor_sync(0xffffffffu, bb, s);
    }
    if (lane == 0) { redA[w] = aa; redB[w] = bb; }
    __syncthreads();
    if (tid == 0) {
        float sA2 = ((redA[0] + redA[1]) + (redA[2] + redA[3]))
                  + ((redA[4] + redA[5]) + (redA[6] + redA[7]));
        float sB2 = ((redB[0] + redB[1]) + (redB[2] + redB[3]))
                  + ((redB[4] + redB[5]) + (redB[6] + redB[7]));
        g_pA[blockIdx.x] = sA2; g_pB[blockIdx.x] = sB2;
    }
}

__global__ void finalize_kernel(float* __restrict__ out)
{
    __shared__ float rA[128], rB[128];
    int tid = threadIdx.x;
    rA[tid] = g_pA[tid]; rB[tid] = g_pB[tid];
    __syncthreads();
    for (int s = 64; s > 0; s >>= 1) {
        if (tid < s) { rA[tid] += rA[tid + s]; rB[tid] += rB[tid + s]; }
        __syncthreads();
    }
    if (tid == 0) {
        float lp  = rA[0] / (float)BATCH;
        float lpi = lp + rB[0] / (float)BATCH;
        unsigned base = (unsigned)(NSTEPS + 1) * BATCH * 5u;
        out[base + 0] = lp;
        out[base + 1] = lpi;
    }
}

extern "C" void kernel_launch(void* const* d_in, const int* in_sizes, int n_in,
                              void* d_out, int out_size)
{
    const float* dw  = (const float*)d_in[0];
    const float* X0  = (const float*)d_in[1];
    const float* R0  = (const float*)d_in[2];
    const float* pW1 = (const float*)d_in[3];  const float* pb1 = (const float*)d_in[4];
    const float* pW2 = (const float*)d_in[5];  const float* pb2 = (const float*)d_in[6];
    const float* pW3 = (const float*)d_in[7];  const float* pb3 = (const float*)d_in[8];
    const float* qW1 = (const float*)d_in[9];  const float* qb1 = (const float*)d_in[10];
    const float* qW2 = (const float*)d_in[11]; const float* qb2 = (const float*)d_in[12];
    const float* qW3 = (const float*)d_in[13]; const float* qb3 = (const float*)d_in[14];
    float* out = (float*)d_out;

    sim_kernel<<<128, 256>>>(dw, X0, R0, pW1, pb1, pW2, pb2, pW3, pb3,
                             qW1, qb1, qW2, qb2, qW3, qb3, out);
    finalize_kernel<<<1, 128>>>(out);
}

// round 10
// speedup vs baseline: 1.8442x; 1.0965x over previous
#include <cuda_runtime.h>
#include <cuda_bf16.h>

#define HID    64
#define BATCH  16384
#define NSTEPS 100
#define DT     0.01f
#define SPB    64          // samples per block
#define NBLK   256         // BATCH / SPB
#define AP_STRIDE 72       // 64 + 8 pad: (8kt+tg)*72+g -> banks 8tg+g all distinct

__device__ float g_pA[NBLK];
__device__ float g_pB[NBLK];

__device__ __forceinline__ float exact_tanh(float v) {
    float av = fabsf(v);
    float e  = __expf(-2.0f * av);
    float r  = __fdividef(1.0f - e, 1.0f + e);
    return copysignf(r, v);
}
__device__ __forceinline__ float tanh_ap(float x) {
    float y; asm("tanh.approx.f32 %0, %1;" : "=f"(y) : "f"(x)); return y;
}
__device__ __forceinline__ unsigned pack_bf2(float lo, float hi) {
    __nv_bfloat162 v = __floats2bfloat162_rn(lo, hi);
    return *reinterpret_cast<unsigned*>(&v);
}
__device__ __forceinline__ void mma_bf16(float* c,
                                         unsigned a0, unsigned a1, unsigned a2, unsigned a3,
                                         unsigned b0, unsigned b1) {
    asm volatile("mma.sync.aligned.m16n8k16.row.col.f32.bf16.bf16.f32 "
                 "{%0,%1,%2,%3},{%4,%5,%6,%7},{%8,%9},{%0,%1,%2,%3};"
                 : "+f"(c[0]), "+f"(c[1]), "+f"(c[2]), "+f"(c[3])
                 : "r"(a0), "r"(a1), "r"(a2), "r"(a3), "r"(b0), "r"(b1));
}

__global__ void __launch_bounds__(128) sim_kernel(
    const float* __restrict__ dw,
    const float* __restrict__ X0, const float* __restrict__ R0,
    const float* __restrict__ pW1, const float* __restrict__ pb1,
    const float* __restrict__ pW2, const float* __restrict__ pb2,
    const float* __restrict__ pW3, const float* __restrict__ pb3,
    const float* __restrict__ qW1, const float* __restrict__ qb1,
    const float* __restrict__ qW2, const float* __restrict__ qb2,
    const float* __restrict__ qW3, const float* __restrict__ qb3,
    float* __restrict__ out)
{
    __shared__ __align__(16) float4   sW1q[HID];            // {w_t, w_x, w_r, b1}
    __shared__ __align__(16) unsigned aHi[32 * AP_STRIDE];  // bf16x2 h-hi [k2][sample]
    __shared__ __align__(16) unsigned aLo[32 * AP_STRIDE];  // bf16x2 h-lo
    __shared__ __align__(16) float    part[SPB * 4];        // [sample][ng] (2 used)
    __shared__ float  ph1[HID], pd1[HID], ptA[HID], ptB[HID];
    __shared__ float  s_p0, s_dp0, s_pi0, s_b3;
    __shared__ float  redA[4], redB[4];

    const int tid  = threadIdx.x;
    const int lane = tid & 31;
    const int w    = tid >> 5;         // 0..3
    const int g    = lane >> 2;
    const int tg   = lane & 3;
    const int mg   = w >> 1;           // m-group: rows 32mg..32mg+31
    const int ng   = w & 1;            // n-group: cols 32ng..32ng+31

    const float x0v = X0[0], r0v = R0[0];

    for (int k = tid; k < HID; k += 128)
        sW1q[k] = make_float4(qW1[k], qW1[HID + k], qW1[2 * HID + k], qb1[k]);
    if (tid == 0) s_b3 = qb3[0];

    // ---- B fragments (W2 split hi/lo), persistent in registers ----
    unsigned bH0[4][4], bH1[4][4], bL0[4][4], bL1[4][4];
    float b2a[4], b2b[4], w3a[4], w3b[4];
    #pragma unroll
    for (int nt = 0; nt < 4; ++nt) {
        int n = 32 * ng + 8 * nt + g;
        #pragma unroll
        for (int kt = 0; kt < 4; ++kt) {
            int k0 = 16 * kt + 2 * tg;
            float w00 = qW2[(k0 + 0) * HID + n];
            float w01 = qW2[(k0 + 1) * HID + n];
            float w10 = qW2[(k0 + 8) * HID + n];
            float w11 = qW2[(k0 + 9) * HID + n];
            float h00 = __bfloat162float(__float2bfloat16(w00));
            float h01 = __bfloat162float(__float2bfloat16(w01));
            float h10 = __bfloat162float(__float2bfloat16(w10));
            float h11 = __bfloat162float(__float2bfloat16(w11));
            bH0[nt][kt] = pack_bf2(h00, h01);
            bH1[nt][kt] = pack_bf2(h10, h11);
            bL0[nt][kt] = pack_bf2(w00 - h00, w01 - h01);
            bL1[nt][kt] = pack_bf2(w10 - h10, w11 - h11);
        }
        int jc = 32 * ng + 8 * nt + 2 * tg;
        b2a[nt] = qb2[jc];     b2b[nt] = qb2[jc + 1];
        w3a[nt] = qW3[jc];     w3b[nt] = qW3[jc + 1];
    }

    // ---- scalar prep (p0, dp0, pi0), exact tanh ----
    if (tid < HID) {
        int j = tid;
        float a = pW1[HID + j] * x0v + pW1[2 * HID + j] * r0v + pb1[j];
        float h = exact_tanh(a);
        ph1[j] = h;
        pd1[j] = (1.0f - h * h) * pW1[HID + j];
        float aq = qW1[HID + j] * x0v + qW1[2 * HID + j] * r0v + qb1[j];
        ptA[j] = exact_tanh(aq);
    }
    __syncthreads();
    float pa = 0.0f, qa = 0.0f, db = 0.0f;
    if (tid < HID) {
        int j = tid;
        float acc = pb2[j], dacc = 0.0f, accq = qb2[j];
        #pragma unroll 16
        for (int k = 0; k < HID; ++k) {
            float wv = pW2[k * HID + j];
            acc  += ph1[k] * wv;
            dacc += pd1[k] * wv;
            accq += ptA[k] * qW2[k * HID + j];
        }
        float h2 = exact_tanh(acc);
        float d2 = (1.0f - h2 * h2) * dacc;
        pa = h2 * pW3[j];
        db = d2 * pW3[j];
        qa = exact_tanh(accq) * qW3[j];
    }
    __syncthreads();
    if (tid < HID) { ph1[tid] = pa; pd1[tid] = qa; ptB[tid] = db; }
    __syncthreads();
    if (tid == 0) {
        float s = pb3[0], sd = 0.0f, sq = qb3[0];
        for (int k = 0; k < HID; ++k) { s += ph1[k]; sd += ptB[k]; sq += pd1[k]; }
        s_p0 = s; s_dp0 = sd; s_pi0 = sq;
    }
    __syncthreads();

    const float p0  = s_p0;
    const float dp0 = s_dp0;
    const float pi0 = s_pi0;
    const float b3v = s_b3;

    const float C_ADT  = 0.05f * 0.01f;
    const float C_STDT = 0.2f * 0.3f * 0.01f;
    const float SIG    = 0.2f;
    const float BEFF   = 0.1f;
    const float C_R1   = 0.02f - 0.5f * 0.1f * 0.1f;
    const float C_P1   = -(0.05f + 0.5f * 0.3f * 0.3f);
    const float TH     = 0.3f;

    // both halfk threads duplicate the full state of sample sA (bitwise identical)
    const int sA    = tid >> 1;        // 0..63
    const int halfk = tid & 1;
    const int b = blockIdx.x * SPB + sA;

    float x = x0v, mn = x0v, Wsum = 0.0f, pi = pi0, Rv = r0v, p = p0;
    float dwv = dw[b * NSTEPS];
    if (halfk == 0) {
        unsigned base = (unsigned)b * 5u;
        out[base + 0] = x0v; out[base + 1] = r0v; out[base + 2] = pi0;
        out[base + 3] = -p0; out[base + 4] = -dp0;
    }

    #pragma unroll 1
    for (int i = 1; i < NSTEPS; ++i) {
        float t = (float)i * DT;
        // ---- fused: gather pi (prev GEMM), store prev row, advance state ----
        if (i > 1) {
            float2 pr = *reinterpret_cast<const float2*>(part + sA * 4);
            pi = b3v + pr.x + pr.y;
            if (halfk == 0) {
                unsigned base = ((unsigned)(i - 1) * BATCH + (unsigned)b) * 5u;
                out[base + 0] = x;  out[base + 1] = Rv; out[base + 2] = pi;
                out[base + 3] = -p; out[base + 4] = -dp0;
            }
        }
        {
            float dwi = dwv;
            x = x + x * C_ADT + pi * C_STDT + pi * SIG * dwi;
            mn = fminf(mn, x);
            Wsum += dwi;
            Rv = r0v * __expf(C_R1 * t + BEFF * Wsum);
            p  = p0  * __expf(C_P1 * t - TH * Wsum);
            dwv = dw[b * NSTEPS + i];
        }

        // ---- A: hidden layer -> bf16 hi/lo in shared (32 units/thread) ----
        {
            float s0 = 2.0f * t;
            #pragma unroll
            for (int k2 = 0; k2 < 16; ++k2) {
                int k = 32 * halfk + 2 * k2;
                float4 wa = sW1q[k];
                float4 wb = sW1q[k + 1];
                float a0 = fmaf(wa.x, s0, wa.w); a0 = fmaf(wa.y, x, a0); a0 = fmaf(wa.z, Rv, a0);
                float a1 = fmaf(wb.x, s0, wb.w); a1 = fmaf(wb.y, x, a1); a1 = fmaf(wb.z, Rv, a1);
                float h0 = tanh_ap(a0), h1v = tanh_ap(a1);
                float h0h = __bfloat162float(__float2bfloat16(h0));
                float h1h = __bfloat162float(__float2bfloat16(h1v));
                int idx = (16 * halfk + k2) * AP_STRIDE + sA;
                aHi[idx] = pack_bf2(h0h, h1h);
                aLo[idx] = pack_bf2(h0 - h0h, h1v - h1h);
            }
        }
        __syncthreads();

        // ---- GEMM: warp tile 32 rows x 32 cols (2M x 2N over 4 warps) ----
        {
            float c[2][4][4];
            #pragma unroll
            for (int m2 = 0; m2 < 2; ++m2)
                #pragma unroll
                for (int nt = 0; nt < 4; ++nt)
                    #pragma unroll
                    for (int q = 0; q < 4; ++q) c[m2][nt][q] = 0.0f;

            #pragma unroll
            for (int kt = 0; kt < 4; ++kt) {
                #pragma unroll
                for (int m2 = 0; m2 < 2; ++m2) {
                    int base = 32 * mg + 16 * m2;
                    int r0i = (8 * kt + tg) * AP_STRIDE + base + g;
                    int r1i = (8 * kt + tg + 4) * AP_STRIDE + base + g;
                    unsigned a0h = aHi[r0i], a1h = aHi[r0i + 8];
                    unsigned a2h = aHi[r1i], a3h = aHi[r1i + 8];
                    unsigned a0l = aLo[r0i], a1l = aLo[r0i + 8];
                    unsigned a2l = aLo[r1i], a3l = aLo[r1i + 8];
                    #pragma unroll
                    for (int nt = 0; nt < 4; ++nt) {
                        mma_bf16(c[m2][nt], a0h, a1h, a2h, a3h, bH0[nt][kt], bH1[nt][kt]);
                        mma_bf16(c[m2][nt], a0h, a1h, a2h, a3h, bL0[nt][kt], bL1[nt][kt]);
                        mma_bf16(c[m2][nt], a0l, a1l, a2l, a3l, bH0[nt][kt], bH1[nt][kt]);
                    }
                }
            }
            // epilogue: tanh, W3 dot, reduce over tg
            #pragma unroll
            for (int m2 = 0; m2 < 2; ++m2) {
                float vl = 0.0f, vh = 0.0f;
                #pragma unroll
                for (int nt = 0; nt < 4; ++nt) {
                    vl += fmaf(tanh_ap(c[m2][nt][0] + b2a[nt]), w3a[nt],
                               tanh_ap(c[m2][nt][1] + b2b[nt]) * w3b[nt]);
                    vh += fmaf(tanh_ap(c[m2][nt][2] + b2a[nt]), w3a[nt],
                               tanh_ap(c[m2][nt][3] + b2b[nt]) * w3b[nt]);
                }
                vl += __shfl_xor_sync(0xffffffffu, vl, 1);
                vh += __shfl_xor_sync(0xffffffffu, vh, 1);
                vl += __shfl_xor_sync(0xffffffffu, vl, 2);
                vh += __shfl_xor_sync(0xffffffffu, vh, 2);
                if (tg == 0) {
                    int base = 32 * mg + 16 * m2;
                    part[(base + g) * 4 + ng]     = vl;
                    part[(base + g + 8) * 4 + ng] = vh;
                }
            }
        }
        __syncthreads();
    }

    // ---- tail: gather pi at t_99, store row 99; final step to t_100 ----
    {
        float2 pr = *reinterpret_cast<const float2*>(part + sA * 4);
        pi = b3v + pr.x + pr.y;
        if (halfk == 0) {
            unsigned base = ((unsigned)(NSTEPS - 1) * BATCH + (unsigned)b) * 5u;
            out[base + 0] = x;  out[base + 1] = Rv; out[base + 2] = pi;
            out[base + 3] = -p; out[base + 4] = -dp0;
        }
        float t = (float)NSTEPS * DT;
        float dwi = dwv;
        x = x + x * C_ADT + pi * C_STDT + pi * SIG * dwi;
        mn = fminf(mn, x);
        Wsum += dwi;
        Rv = r0v * __expf(C_R1 * t + BEFF * Wsum);
        p  = p0  * __expf(C_P1 * t - TH * Wsum);
        if (halfk == 0) {
            unsigned base = ((unsigned)NSTEPS * BATCH + (unsigned)b) * 5u;
            out[base + 0] = x;  out[base + 1] = Rv; out[base + 2] = pi;
            out[base + 3] = -p; out[base + 4] = -dp0;
        }
    }

    // ---- losses (halfk==0 contributes; halves are duplicates) ----
    float aa = 0.0f, bb = 0.0f;
    if (halfk == 0) {
        float xc  = fmaxf(x, 1e-6f);
        float ux  = Rv * rsqrtf(xc);
        float uv  = 2.0f * Rv * sqrtf(xc);
        float dpn = fmaxf(1e-6f - mn, 0.0f);
        float pen = 100.0f * dpn * dpn;
        aa = p + ux; aa = aa * aa + pen;
        bb = -uv + pen;
    }
    #pragma unroll
    for (int s = 16; s > 0; s >>= 1) {
        aa += __shfl_xor_sync(0xffffffffu, aa, s);
        bb += __shfl_xor_sync(0xffffffffu, bb, s);
    }
    if (lane == 0) { redA[w] = aa; redB[w] = bb; }
    __syncthreads();
    if (tid == 0) {
        g_pA[blockIdx.x] = (redA[0] + redA[1]) + (redA[2] + redA[3]);
        g_pB[blockIdx.x] = (redB[0] + redB[1]) + (redB[2] + redB[3]);
    }
}

__global__ void finalize_kernel(float* __restrict__ out)
{
    __shared__ float rA[NBLK], rB[NBLK];
    int tid = threadIdx.x;
    rA[tid] = g_pA[tid]; rB[tid] = g_pB[tid];
    __syncthreads();
    for (int s = NBLK / 2; s > 0; s >>= 1) {
        if (tid < s) { rA[tid] += rA[tid + s]; rB[tid] += rB[tid + s]; }
        __syncthreads();
    }
    if (tid == 0) {
        float lp  = rA[0] / (float)BATCH;
        float lpi = lp + rB[0] / (float)BATCH;
        unsigned base = (unsigned)(NSTEPS + 1) * BATCH * 5u;
        out[base + 0] = lp;
        out[base + 1] = lpi;
    }
}

extern "C" void kernel_launch(void* const* d_in, const int* in_sizes, int n_in,
                              void* d_out, int out_size)
{
    const float* dw  = (const float*)d_in[0];
    const float* X0  = (const float*)d_in[1];
    const float* R0  = (const float*)d_in[2];
    const float* pW1 = (const float*)d_in[3];  const float* pb1 = (const float*)d_in[4];
    const float* pW2 = (const float*)d_in[5];  const float* pb2 = (const float*)d_in[6];
    const float* pW3 = (const float*)d_in[7];  const float* pb3 = (const float*)d_in[8];
    const float* qW1 = (const float*)d_in[9];  const float* qb1 = (const float*)d_in[10];
    const float* qW2 = (const float*)d_in[11]; const float* qb2 = (const float*)d_in[12];
    const float* qW3 = (const float*)d_in[13]; const float* qb3 = (const float*)d_in[14];
    float* out = (float*)d_out;

    sim_kernel<<<NBLK, 128>>>(dw, X0, R0, pW1, pb1, pW2, pb2, pW3, pb3,
                              qW1, qb1, qW2, qb2, qW3, qb3, out);
    finalize_kernel<<<1, NBLK>>>(out);
}

// round 11
// speedup vs baseline: 2.0268x; 1.0990x over previous
#include <cuda_runtime.h>
#include <cuda_bf16.h>
#include <cuda_fp16.h>

#define HID    64
#define BATCH  16384
#define NSTEPS 100
#define DT     0.01f
#define SPB    64          // samples per block
#define NBLK   256         // BATCH / SPB
#define AP_STRIDE 72       // 64 + 8 pad: (8kt+tg)*72+g -> banks 8tg+g all distinct

__device__ float g_pA[NBLK];
__device__ float g_pB[NBLK];

__device__ __forceinline__ float exact_tanh(float v) {
    float av = fabsf(v);
    float e  = __expf(-2.0f * av);
    float r  = __fdividef(1.0f - e, 1.0f + e);
    return copysignf(r, v);
}
__device__ __forceinline__ float tanh_ap(float x) {
    float y; asm("tanh.approx.f32 %0, %1;" : "=f"(y) : "f"(x)); return y;
}
__device__ __forceinline__ unsigned pack_hf2(float lo, float hi) {
    __half2 v = __floats2half2_rn(lo, hi);
    return *reinterpret_cast<unsigned*>(&v);
}
__device__ __forceinline__ void mma_f16(float* c,
                                        unsigned a0, unsigned a1, unsigned a2, unsigned a3,
                                        unsigned b0, unsigned b1) {
    asm volatile("mma.sync.aligned.m16n8k16.row.col.f32.f16.f16.f32 "
                 "{%0,%1,%2,%3},{%4,%5,%6,%7},{%8,%9},{%0,%1,%2,%3};"
                 : "+f"(c[0]), "+f"(c[1]), "+f"(c[2]), "+f"(c[3])
                 : "r"(a0), "r"(a1), "r"(a2), "r"(a3), "r"(b0), "r"(b1));
}

__global__ void __launch_bounds__(128) sim_kernel(
    const float* __restrict__ dw,
    const float* __restrict__ X0, const float* __restrict__ R0,
    const float* __restrict__ pW1, const float* __restrict__ pb1,
    const float* __restrict__ pW2, const float* __restrict__ pb2,
    const float* __restrict__ pW3, const float* __restrict__ pb3,
    const float* __restrict__ qW1, const float* __restrict__ qb1,
    const float* __restrict__ qW2, const float* __restrict__ qb2,
    const float* __restrict__ qW3, const float* __restrict__ qb3,
    float* __restrict__ out)
{
    __shared__ __align__(16) float4   sW1q[HID];            // {w_t, w_x, w_r, b1}
    __shared__ __align__(16) unsigned aH[32 * AP_STRIDE];   // f16x2 h [k2][sample]
    __shared__ __align__(16) float    part[SPB * 4];        // [sample][ng] (2 used)
    __shared__ float  ph1[HID], pd1[HID], ptA[HID], ptB[HID];
    __shared__ float  s_p0, s_dp0, s_pi0, s_b3;
    __shared__ float  redA[4], redB[4];

    const int tid  = threadIdx.x;
    const int lane = tid & 31;
    const int w    = tid >> 5;         // 0..3
    const int g    = lane >> 2;
    const int tg   = lane & 3;
    const int mg   = w >> 1;           // m-group: rows 32mg..32mg+31
    const int ng   = w & 1;            // n-group: cols 32ng..32ng+31

    const float x0v = X0[0], r0v = R0[0];

    for (int k = tid; k < HID; k += 128)
        sW1q[k] = make_float4(qW1[k], qW1[HID + k], qW1[2 * HID + k], qb1[k]);
    if (tid == 0) s_b3 = qb3[0];

    // ---- B fragments: W2 split into fp16 hi + fp16 residual, in registers ----
    unsigned bH0[4][4], bH1[4][4], bL0[4][4], bL1[4][4];
    float b2a[4], b2b[4], w3a[4], w3b[4];
    #pragma unroll
    for (int nt = 0; nt < 4; ++nt) {
        int n = 32 * ng + 8 * nt + g;
        #pragma unroll
        for (int kt = 0; kt < 4; ++kt) {
            int k0 = 16 * kt + 2 * tg;
            float w00 = qW2[(k0 + 0) * HID + n];
            float w01 = qW2[(k0 + 1) * HID + n];
            float w10 = qW2[(k0 + 8) * HID + n];
            float w11 = qW2[(k0 + 9) * HID + n];
            float h00 = __half2float(__float2half_rn(w00));
            float h01 = __half2float(__float2half_rn(w01));
            float h10 = __half2float(__float2half_rn(w10));
            float h11 = __half2float(__float2half_rn(w11));
            bH0[nt][kt] = pack_hf2(h00, h01);
            bH1[nt][kt] = pack_hf2(h10, h11);
            bL0[nt][kt] = pack_hf2(w00 - h00, w01 - h01);
            bL1[nt][kt] = pack_hf2(w10 - h10, w11 - h11);
        }
        int jc = 32 * ng + 8 * nt + 2 * tg;
        b2a[nt] = qb2[jc];     b2b[nt] = qb2[jc + 1];
        w3a[nt] = qW3[jc];     w3b[nt] = qW3[jc + 1];
    }

    // ---- scalar prep (p0, dp0, pi0), exact tanh ----
    if (tid < HID) {
        int j = tid;
        float a = pW1[HID + j] * x0v + pW1[2 * HID + j] * r0v + pb1[j];
        float h = exact_tanh(a);
        ph1[j] = h;
        pd1[j] = (1.0f - h * h) * pW1[HID + j];
        float aq = qW1[HID + j] * x0v + qW1[2 * HID + j] * r0v + qb1[j];
        ptA[j] = exact_tanh(aq);
    }
    __syncthreads();
    float pa = 0.0f, qa = 0.0f, db = 0.0f;
    if (tid < HID) {
        int j = tid;
        float acc = pb2[j], dacc = 0.0f, accq = qb2[j];
        #pragma unroll 16
        for (int k = 0; k < HID; ++k) {
            float wv = pW2[k * HID + j];
            acc  += ph1[k] * wv;
            dacc += pd1[k] * wv;
            accq += ptA[k] * qW2[k * HID + j];
        }
        float h2 = exact_tanh(acc);
        float d2 = (1.0f - h2 * h2) * dacc;
        pa = h2 * pW3[j];
        db = d2 * pW3[j];
        qa = exact_tanh(accq) * qW3[j];
    }
    __syncthreads();
    if (tid < HID) { ph1[tid] = pa; pd1[tid] = qa; ptB[tid] = db; }
    __syncthreads();
    if (tid == 0) {
        float s = pb3[0], sd = 0.0f, sq = qb3[0];
        for (int k = 0; k < HID; ++k) { s += ph1[k]; sd += ptB[k]; sq += pd1[k]; }
        s_p0 = s; s_dp0 = sd; s_pi0 = sq;
    }
    __syncthreads();

    const float p0  = s_p0;
    const float dp0 = s_dp0;
    const float pi0 = s_pi0;
    const float b3v = s_b3;

    const float C_ADT  = 0.05f * 0.01f;
    const float C_STDT = 0.2f * 0.3f * 0.01f;
    const float SIG    = 0.2f;
    const float BEFF   = 0.1f;
    const float C_R1   = 0.02f - 0.5f * 0.1f * 0.1f;
    const float C_P1   = -(0.05f + 0.5f * 0.3f * 0.3f);
    const float TH     = 0.3f;

    // both halfk threads duplicate the full state of sample sA (bitwise identical)
    const int sA    = tid >> 1;        // 0..63
    const int halfk = tid & 1;
    const int b = blockIdx.x * SPB + sA;

    float x = x0v, mn = x0v, Wsum = 0.0f, pi = pi0, Rv = r0v, p = p0;
    float dwv = dw[b * NSTEPS];
    if (halfk == 0) {
        unsigned base = (unsigned)b * 5u;
        out[base + 0] = x0v; out[base + 1] = r0v; out[base + 2] = pi0;
        out[base + 3] = -p0; out[base + 4] = -dp0;
    }

    #pragma unroll 1
    for (int i = 1; i < NSTEPS; ++i) {
        float t = (float)i * DT;
        // ---- fused: gather pi (prev GEMM), store prev row, advance state ----
        if (i > 1) {
            float2 pr = *reinterpret_cast<const float2*>(part + sA * 4);
            pi = b3v + pr.x + pr.y;
            if (halfk == 0) {
                unsigned base = ((unsigned)(i - 1) * BATCH + (unsigned)b) * 5u;
                out[base + 0] = x;  out[base + 1] = Rv; out[base + 2] = pi;
                out[base + 3] = -p; out[base + 4] = -dp0;
            }
        }
        {
            float dwi = dwv;
            x = x + x * C_ADT + pi * C_STDT + pi * SIG * dwi;
            mn = fminf(mn, x);
            Wsum += dwi;
            Rv = r0v * __expf(C_R1 * t + BEFF * Wsum);
            p  = p0  * __expf(C_P1 * t - TH * Wsum);
            dwv = dw[b * NSTEPS + i];
        }

        // ---- A: hidden layer -> single fp16 in shared (32 units/thread) ----
        {
            float s0 = 2.0f * t;
            #pragma unroll
            for (int k2 = 0; k2 < 16; ++k2) {
                int k = 32 * halfk + 2 * k2;
                float4 wa = sW1q[k];
                float4 wb = sW1q[k + 1];
                float a0 = fmaf(wa.x, s0, wa.w); a0 = fmaf(wa.y, x, a0); a0 = fmaf(wa.z, Rv, a0);
                float a1 = fmaf(wb.x, s0, wb.w); a1 = fmaf(wb.y, x, a1); a1 = fmaf(wb.z, Rv, a1);
                float h0 = tanh_ap(a0), h1v = tanh_ap(a1);
                aH[(16 * halfk + k2) * AP_STRIDE + sA] = pack_hf2(h0, h1v);
            }
        }
        __syncthreads();

        // ---- GEMM: warp tile 32 rows x 32 cols (2M x 2N over 4 warps) ----
        {
            float c[2][4][4];
            #pragma unroll
            for (int m2 = 0; m2 < 2; ++m2)
                #pragma unroll
                for (int nt = 0; nt < 4; ++nt)
                    #pragma unroll
                    for (int q = 0; q < 4; ++q) c[m2][nt][q] = 0.0f;

            #pragma unroll
            for (int kt = 0; kt < 4; ++kt) {
                #pragma unroll
                for (int m2 = 0; m2 < 2; ++m2) {
                    int base = 32 * mg + 16 * m2;
                    int r0i = (8 * kt + tg) * AP_STRIDE + base + g;
                    int r1i = (8 * kt + tg + 4) * AP_STRIDE + base + g;
                    unsigned a0 = aH[r0i], a1 = aH[r0i + 8];
                    unsigned a2 = aH[r1i], a3 = aH[r1i + 8];
                    #pragma unroll
                    for (int nt = 0; nt < 4; ++nt) {
                        mma_f16(c[m2][nt], a0, a1, a2, a3, bH0[nt][kt], bH1[nt][kt]);
                        mma_f16(c[m2][nt], a0, a1, a2, a3, bL0[nt][kt], bL1[nt][kt]);
                    }
                }
            }
            // epilogue: tanh, W3 dot, reduce over tg
            #pragma unroll
            for (int m2 = 0; m2 < 2; ++m2) {
                float vl = 0.0f, vh = 0.0f;
                #pragma unroll
                for (int nt = 0; nt < 4; ++nt) {
                    vl += fmaf(tanh_ap(c[m2][nt][0] + b2a[nt]), w3a[nt],
                               tanh_ap(c[m2][nt][1] + b2b[nt]) * w3b[nt]);
                    vh += fmaf(tanh_ap(c[m2][nt][2] + b2a[nt]), w3a[nt],
                               tanh_ap(c[m2][nt][3] + b2b[nt]) * w3b[nt]);
                }
                vl += __shfl_xor_sync(0xffffffffu, vl, 1);
                vh += __shfl_xor_sync(0xffffffffu, vh, 1);
                vl += __shfl_xor_sync(0xffffffffu, vl, 2);
                vh += __shfl_xor_sync(0xffffffffu, vh, 2);
                if (tg == 0) {
                    int base = 32 * mg + 16 * m2;
                    part[(base + g) * 4 + ng]     = vl;
                    part[(base + g + 8) * 4 + ng] = vh;
                }
            }
        }
        __syncthreads();
    }

    // ---- tail: gather pi at t_99, store row 99; final step to t_100 ----
    {
        float2 pr = *reinterpret_cast<const float2*>(part + sA * 4);
        pi = b3v + pr.x + pr.y;
        if (halfk == 0) {
            unsigned base = ((unsigned)(NSTEPS - 1) * BATCH + (unsigned)b) * 5u;
            out[base + 0] = x;  out[base + 1] = Rv; out[base + 2] = pi;
            out[base + 3] = -p; out[base + 4] = -dp0;
        }
        float t = (float)NSTEPS * DT;
        float dwi = dwv;
        x = x + x * C_ADT + pi * C_STDT + pi * SIG * dwi;
        mn = fminf(mn, x);
        Wsum += dwi;
        Rv = r0v * __expf(C_R1 * t + BEFF * Wsum);
        p  = p0  * __expf(C_P1 * t - TH * Wsum);
        if (halfk == 0) {
            unsigned base = ((unsigned)NSTEPS * BATCH + (unsigned)b) * 5u;
            out[base + 0] = x;  out[base + 1] = Rv; out[base + 2] = pi;
            out[base + 3] = -p; out[base + 4] = -dp0;
        }
    }

    // ---- losses (halfk==0 contributes; halves are duplicates) ----
    float aa = 0.0f, bb = 0.0f;
    if (halfk == 0) {
        float xc  = fmaxf(x, 1e-6f);
        float ux  = Rv * rsqrtf(xc);
        float uv  = 2.0f * Rv * sqrtf(xc);
        float dpn = fmaxf(1e-6f - mn, 0.0f);
        float pen = 100.0f * dpn * dpn;
        aa = p + ux; aa = aa * aa + pen;
        bb = -uv + pen;
    }
    #pragma unroll
    for (int s = 16; s > 0; s >>= 1) {
        aa += __shfl_xor_sync(0xffffffffu, aa, s);
        bb += __shfl_xor_sync(0xffffffffu, bb, s);
    }
    if (lane == 0) { redA[w] = aa; redB[w] = bb; }
    __syncthreads();
    if (tid == 0) {
        g_pA[blockIdx.x] = (redA[0] + redA[1]) + (redA[2] + redA[3]);
        g_pB[blockIdx.x] = (redB[0] + redB[1]) + (redB[2] + redB[3]);
    }
}

__global__ void finalize_kernel(float* __restrict__ out)
{
    __shared__ float rA[NBLK], rB[NBLK];
    int tid = threadIdx.x;
    rA[tid] = g_pA[tid]; rB[tid] = g_pB[tid];
    __syncthreads();
    for (int s = NBLK / 2; s > 0; s >>= 1) {
        if (tid < s) { rA[tid] += rA[tid + s]; rB[tid] += rB[tid + s]; }
        __syncthreads();
    }
    if (tid == 0) {
        float lp  = rA[0] / (float)BATCH;
        float lpi = lp + rB[0] / (float)BATCH;
        unsigned base = (unsigned)(NSTEPS + 1) * BATCH * 5u;
        out[base + 0] = lp;
        out[base + 1] = lpi;
    }
}

extern "C" void kernel_launch(void* const* d_in, const int* in_sizes, int n_in,
                              void* d_out, int out_size)
{
    const float* dw  = (const float*)d_in[0];
    const float* X0  = (const float*)d_in[1];
    const float* R0  = (const float*)d_in[2];
    const float* pW1 = (const float*)d_in[3];  const float* pb1 = (const float*)d_in[4];
    const float* pW2 = (const float*)d_in[5];  const float* pb2 = (const float*)d_in[6];
    const float* pW3 = (const float*)d_in[7];  const float* pb3 = (const float*)d_in[8];
    const float* qW1 = (const float*)d_in[9];  const float* qb1 = (const float*)d_in[10];
    const float* qW2 = (const float*)d_in[11]; const float* qb2 = (const float*)d_in[12];
    const float* qW3 = (const float*)d_in[13]; const float* qb3 = (const float*)d_in[14];
    float* out = (float*)d_out;

    sim_kernel<<<NBLK, 128>>>(dw, X0, R0, pW1, pb1, pW2, pb2, pW3, pb3,
                              qW1, qb1, qW2, qb2, qW3, qb3, out);
    finalize_kernel<<<1, NBLK>>>(out);
}

// round 12
// speedup vs baseline: 2.8268x; 1.3947x over previous
#include <cuda_runtime.h>
#include <cuda_bf16.h>
#include <cuda_fp16.h>

#define HID    64
#define BATCH  16384
#define NSTEPS 100
#define DT     0.01f
#define SPB    64          // samples per block
#define NBLK   256         // BATCH / SPB
#define AP_STRIDE 72       // 64 + 8 pad: (8kt+tg)*72+g -> banks 8tg+g all distinct

__device__ float g_pA[NBLK];
__device__ float g_pB[NBLK];

__device__ __forceinline__ float exact_tanh(float v) {
    float av = fabsf(v);
    float e  = __expf(-2.0f * av);
    float r  = __fdividef(1.0f - e, 1.0f + e);
    return copysignf(r, v);
}
__device__ __forceinline__ float tanh_ap(float x) {
    float y; asm("tanh.approx.f32 %0, %1;" : "=f"(y) : "f"(x)); return y;
}
__device__ __forceinline__ unsigned pack_hf2(float lo, float hi) {
    __half2 v = __floats2half2_rn(lo, hi);
    return *reinterpret_cast<unsigned*>(&v);
}
__device__ __forceinline__ void mma_f16(float* c,
                                        unsigned a0, unsigned a1, unsigned a2, unsigned a3,
                                        unsigned b0, unsigned b1) {
    asm volatile("mma.sync.aligned.m16n8k16.row.col.f32.f16.f16.f32 "
                 "{%0,%1,%2,%3},{%4,%5,%6,%7},{%8,%9},{%0,%1,%2,%3};"
                 : "+f"(c[0]), "+f"(c[1]), "+f"(c[2]), "+f"(c[3])
                 : "r"(a0), "r"(a1), "r"(a2), "r"(a3), "r"(b0), "r"(b1));
}

__global__ void __launch_bounds__(128) sim_kernel(
    const float* __restrict__ dw,
    const float* __restrict__ X0, const float* __restrict__ R0,
    const float* __restrict__ pW1, const float* __restrict__ pb1,
    const float* __restrict__ pW2, const float* __restrict__ pb2,
    const float* __restrict__ pW3, const float* __restrict__ pb3,
    const float* __restrict__ qW1, const float* __restrict__ qb1,
    const float* __restrict__ qW2, const float* __restrict__ qb2,
    const float* __restrict__ qW3, const float* __restrict__ qb3,
    float* __restrict__ out)
{
    __shared__ __align__(16) float4   sW1q[HID];            // {w_t, w_x, w_r, b1}
    __shared__ __align__(16) unsigned aH[32 * AP_STRIDE];   // f16x2 h [k2][sample]
    __shared__ __align__(16) float    part[SPB * 4];        // [sample][ng] (2 used)
    __shared__ float  ph1[HID], pd1[HID], ptA[HID], ptB[HID];
    __shared__ float  s_p0, s_dp0, s_pi0, s_b3;
    __shared__ float  redA[4], redB[4];

    const int tid  = threadIdx.x;
    const int lane = tid & 31;
    const int w    = tid >> 5;         // 0..3
    const int g    = lane >> 2;
    const int tg   = lane & 3;
    const int mg   = w >> 1;           // m-group: rows 32mg..32mg+31
    const int ng   = w & 1;            // n-group: cols 32ng..32ng+31

    const float x0v = X0[0], r0v = R0[0];

    for (int k = tid; k < HID; k += 128)
        sW1q[k] = make_float4(qW1[k], qW1[HID + k], qW1[2 * HID + k], qb1[k]);
    if (tid == 0) s_b3 = qb3[0];

    // ---- B fragments: W2 as single fp16, persistent in registers ----
    unsigned bH0[4][4], bH1[4][4];
    float b2a[4], b2b[4], w3a[4], w3b[4];
    #pragma unroll
    for (int nt = 0; nt < 4; ++nt) {
        int n = 32 * ng + 8 * nt + g;
        #pragma unroll
        for (int kt = 0; kt < 4; ++kt) {
            int k0 = 16 * kt + 2 * tg;
            bH0[nt][kt] = pack_hf2(qW2[(k0 + 0) * HID + n], qW2[(k0 + 1) * HID + n]);
            bH1[nt][kt] = pack_hf2(qW2[(k0 + 8) * HID + n], qW2[(k0 + 9) * HID + n]);
        }
        int jc = 32 * ng + 8 * nt + 2 * tg;
        b2a[nt] = qb2[jc];     b2b[nt] = qb2[jc + 1];
        w3a[nt] = qW3[jc];     w3b[nt] = qW3[jc + 1];
    }

    // ---- scalar prep (p0, dp0, pi0), exact tanh ----
    if (tid < HID) {
        int j = tid;
        float a = pW1[HID + j] * x0v + pW1[2 * HID + j] * r0v + pb1[j];
        float h = exact_tanh(a);
        ph1[j] = h;
        pd1[j] = (1.0f - h * h) * pW1[HID + j];
        float aq = qW1[HID + j] * x0v + qW1[2 * HID + j] * r0v + qb1[j];
        ptA[j] = exact_tanh(aq);
    }
    __syncthreads();
    float pa = 0.0f, qa = 0.0f, db = 0.0f;
    if (tid < HID) {
        int j = tid;
        float acc = pb2[j], dacc = 0.0f, accq = qb2[j];
        #pragma unroll 16
        for (int k = 0; k < HID; ++k) {
            float wv = pW2[k * HID + j];
            acc  += ph1[k] * wv;
            dacc += pd1[k] * wv;
            accq += ptA[k] * qW2[k * HID + j];
        }
        float h2 = exact_tanh(acc);
        float d2 = (1.0f - h2 * h2) * dacc;
        pa = h2 * pW3[j];
        db = d2 * pW3[j];
        qa = exact_tanh(accq) * qW3[j];
    }
    __syncthreads();
    if (tid < HID) { ph1[tid] = pa; pd1[tid] = qa; ptB[tid] = db; }
    __syncthreads();
    if (tid == 0) {
        float s = pb3[0], sd = 0.0f, sq = qb3[0];
        for (int k = 0; k < HID; ++k) { s += ph1[k]; sd += ptB[k]; sq += pd1[k]; }
        s_p0 = s; s_dp0 = sd; s_pi0 = sq;
    }
    __syncthreads();

    const float p0  = s_p0;
    const float dp0 = s_dp0;
    const float pi0 = s_pi0;
    const float b3v = s_b3;

    const float C_ADT  = 0.05f * 0.01f;
    const float C_STDT = 0.2f * 0.3f * 0.01f;
    const float SIG    = 0.2f;
    const float BEFF   = 0.1f;
    const float C_R1   = 0.02f - 0.5f * 0.1f * 0.1f;
    const float C_P1   = -(0.05f + 0.5f * 0.3f * 0.3f);
    const float TH     = 0.3f;

    // both halfk threads duplicate the full state of sample sA (bitwise identical)
    const int sA    = tid >> 1;        // 0..63
    const int halfk = tid & 1;
    const int b = blockIdx.x * SPB + sA;

    float x = x0v, mn = x0v, Wsum = 0.0f, pi = pi0, Rv = r0v, p = p0;
    float dwv = dw[b * NSTEPS];
    if (halfk == 0) {
        unsigned base = (unsigned)b * 5u;
        out[base + 0] = x0v; out[base + 1] = r0v; out[base + 2] = pi0;
        out[base + 3] = -p0; out[base + 4] = -dp0;
    }

    #pragma unroll 1
    for (int i = 1; i < NSTEPS; ++i) {
        float t = (float)i * DT;
        // ---- fused: gather pi (prev GEMM), store prev row, advance state ----
        if (i > 1) {
            float2 pr = *reinterpret_cast<const float2*>(part + sA * 4);
            pi = b3v + pr.x + pr.y;
            if (halfk == 0) {
                unsigned base = ((unsigned)(i - 1) * BATCH + (unsigned)b) * 5u;
                out[base + 0] = x;  out[base + 1] = Rv; out[base + 2] = pi;
                out[base + 3] = -p; out[base + 4] = -dp0;
            }
        }
        {
            float dwi = dwv;
            x = x + x * C_ADT + pi * C_STDT + pi * SIG * dwi;
            mn = fminf(mn, x);
            Wsum += dwi;
            Rv = r0v * __expf(C_R1 * t + BEFF * Wsum);
            p  = p0  * __expf(C_P1 * t - TH * Wsum);
            dwv = dw[b * NSTEPS + i];
        }

        // ---- A: hidden layer -> single fp16 in shared (32 units/thread) ----
        {
            float s0 = 2.0f * t;
            #pragma unroll
            for (int k2 = 0; k2 < 16; ++k2) {
                int k = 32 * halfk + 2 * k2;
                float4 wa = sW1q[k];
                float4 wb = sW1q[k + 1];
                float a0 = fmaf(wa.x, s0, wa.w); a0 = fmaf(wa.y, x, a0); a0 = fmaf(wa.z, Rv, a0);
                float a1 = fmaf(wb.x, s0, wb.w); a1 = fmaf(wb.y, x, a1); a1 = fmaf(wb.z, Rv, a1);
                float h0 = tanh_ap(a0), h1v = tanh_ap(a1);
                aH[(16 * halfk + k2) * AP_STRIDE + sA] = pack_hf2(h0, h1v);
            }
        }
        __syncthreads();

        // ---- GEMM: warp tile 32 rows x 32 cols (2M x 2N over 4 warps) ----
        {
            // bias folded into accumulator init: c[0],c[2] get col jc; c[1],c[3] col jc+1
            float c[2][4][4];
            #pragma unroll
            for (int m2 = 0; m2 < 2; ++m2)
                #pragma unroll
                for (int nt = 0; nt < 4; ++nt) {
                    c[m2][nt][0] = b2a[nt]; c[m2][nt][1] = b2b[nt];
                    c[m2][nt][2] = b2a[nt]; c[m2][nt][3] = b2b[nt];
                }

            #pragma unroll
            for (int kt = 0; kt < 4; ++kt) {
                #pragma unroll
                for (int m2 = 0; m2 < 2; ++m2) {
                    int base = 32 * mg + 16 * m2;
                    int r0i = (8 * kt + tg) * AP_STRIDE + base + g;
                    int r1i = (8 * kt + tg + 4) * AP_STRIDE + base + g;
                    unsigned a0 = aH[r0i], a1 = aH[r0i + 8];
                    unsigned a2 = aH[r1i], a3 = aH[r1i + 8];
                    #pragma unroll
                    for (int nt = 0; nt < 4; ++nt)
                        mma_f16(c[m2][nt], a0, a1, a2, a3, bH0[nt][kt], bH1[nt][kt]);
                }
            }
            // epilogue: tanh, W3 dot, reduce over tg
            #pragma unroll
            for (int m2 = 0; m2 < 2; ++m2) {
                float vl = 0.0f, vh = 0.0f;
                #pragma unroll
                for (int nt = 0; nt < 4; ++nt) {
                    vl += fmaf(tanh_ap(c[m2][nt][0]), w3a[nt],
                               tanh_ap(c[m2][nt][1]) * w3b[nt]);
                    vh += fmaf(tanh_ap(c[m2][nt][2]), w3a[nt],
                               tanh_ap(c[m2][nt][3]) * w3b[nt]);
                }
                vl += __shfl_xor_sync(0xffffffffu, vl, 1);
                vh += __shfl_xor_sync(0xffffffffu, vh, 1);
                vl += __shfl_xor_sync(0xffffffffu, vl, 2);
                vh += __shfl_xor_sync(0xffffffffu, vh, 2);
                if (tg == 0) {
                    int base = 32 * mg + 16 * m2;
                    part[(base + g) * 4 + ng]     = vl;
                    part[(base + g + 8) * 4 + ng] = vh;
                }
            }
        }
        __syncthreads();
    }

    // ---- tail: gather pi at t_99, store row 99; final step to t_100 ----
    {
        float2 pr = *reinterpret_cast<const float2*>(part + sA * 4);
        pi = b3v + pr.x + pr.y;
        if (halfk == 0) {
            unsigned base = ((unsigned)(NSTEPS - 1) * BATCH + (unsigned)b) * 5u;
            out[base + 0] = x;  out[base + 1] = Rv; out[base + 2] = pi;
            out[base + 3] = -p; out[base + 4] = -dp0;
        }
        float t = (float)NSTEPS * DT;
        float dwi = dwv;
        x = x + x * C_ADT + pi * C_STDT + pi * SIG * dwi;
        mn = fminf(mn, x);
        Wsum += dwi;
        Rv = r0v * __expf(C_R1 * t + BEFF * Wsum);
        p  = p0  * __expf(C_P1 * t - TH * Wsum);
        if (halfk == 0) {
            unsigned base = ((unsigned)NSTEPS * BATCH + (unsigned)b) * 5u;
            out[base + 0] = x;  out[base + 1] = Rv; out[base + 2] = pi;
            out[base + 3] = -p; out[base + 4] = -dp0;
        }
    }

    // ---- losses (halfk==0 contributes; halves are duplicates) ----
    float aa = 0.0f, bb = 0.0f;
    if (halfk == 0) {
        float xc  = fmaxf(x, 1e-6f);
        float ux  = Rv * rsqrtf(xc);
        float uv  = 2.0f * Rv * sqrtf(xc);
        float dpn = fmaxf(1e-6f - mn, 0.0f);
        float pen = 100.0f * dpn * dpn;
        aa = p + ux; aa = aa * aa + pen;
        bb = -uv + pen;
    }
    #pragma unroll
    for (int s = 16; s > 0; s >>= 1) {
        aa += __shfl_xor_sync(0xffffffffu, aa, s);
        bb += __shfl_xor_sync(0xffffffffu, bb, s);
    }
    if (lane == 0) { redA[w] = aa; redB[w] = bb; }
    __syncthreads();
    if (tid == 0) {
        g_pA[blockIdx.x] = (redA[0] + redA[1]) + (redA[2] + redA[3]);
        g_pB[blockIdx.x] = (redB[0] + redB[1]) + (redB[2] + redB[3]);
    }
}

__global__ void finalize_kernel(float* __restrict__ out)
{
    __shared__ float rA[NBLK], rB[NBLK];
    int tid = threadIdx.x;
    rA[tid] = g_pA[tid]; rB[tid] = g_pB[tid];
    __syncthreads();
    for (int s = NBLK / 2; s > 0; s >>= 1) {
        if (tid < s) { rA[tid] += rA[tid + s]; rB[tid] += rB[tid + s]; }
        __syncthreads();
    }
    if (tid == 0) {
        float lp  = rA[0] / (float)BATCH;
        float lpi = lp + rB[0] / (float)BATCH;
        unsigned base = (unsigned)(NSTEPS + 1) * BATCH * 5u;
        out[base + 0] = lp;
        out[base + 1] = lpi;
    }
}

extern "C" void kernel_launch(void* const* d_in, const int* in_sizes, int n_in,
                              void* d_out, int out_size)
{
    const float* dw  = (const float*)d_in[0];
    const float* X0  = (const float*)d_in[1];
    const float* R0  = (const float*)d_in[2];
    const float* pW1 = (const float*)d_in[3];  const float* pb1 = (const float*)d_in[4];
    const float* pW2 = (const float*)d_in[5];  const float* pb2 = (const float*)d_in[6];
    const float* pW3 = (const float*)d_in[7];  const float* pb3 = (const float*)d_in[8];
    const float* qW1 = (const float*)d_in[9];  const float* qb1 = (const float*)d_in[10];
    const float* qW2 = (const float*)d_in[11]; const float* qb2 = (const float*)d_in[12];
    const float* qW3 = (const float*)d_in[13]; const float* qb3 = (const float*)d_in[14];
    float* out = (float*)d_out;

    sim_kernel<<<NBLK, 128>>>(dw, X0, R0, pW1, pb1, pW2, pb2, pW3, pb3,
                              qW1, qb1, qW2, qb2, qW3, qb3, out);
    finalize_kernel<<<1, NBLK>>>(out);
}